// round 13
// baseline (speedup 1.0000x reference)
#include <cuda_runtime.h>
#include <math.h>
#include <stdint.h>

#define NTOK 16384
#define DM   2048
#define NE   64
#define CAP  640
#define BT   128
#define KB   16
#define NSPLIT 8
#define KSL  (DM / NSPLIT)     // 256
#define NCHS (KSL / KB)        // 16

#define XSTR 148
#define WSTR 68
#define XCOL(t) ((t) + 4 * ((t) >> 5))

// ---------------- device scratch (zero-init; reset in-kernel for replays) ----------------
__device__ int   g_e12[NTOK];
__device__ float g_w12[2 * NTOK];
__device__ int   g_cnt1[NE];
__device__ float g_counts[NE];
__device__ float g_zsum;
__device__ int   g_tilecnt[128];
__device__ int   g_done;
__device__ float g_part[NSPLIT * NTOK * NE];   // 33.5 MB

// ---------------- stage A: K-split GEMM + last-finisher fused reduce/softmax/top2 ----------------
__global__ __launch_bounds__(128) void gemm_router(
    const float* __restrict__ x, const float* __restrict__ W,
    float* __restrict__ out_rw)
{
    __shared__ __align__(16) float xs[2 * KB * XSTR];
    __shared__ __align__(16) float ws[2 * KB * WSTR];
    __shared__ int slast;

    const int tid = threadIdx.x;
    const int tg  = tid & 15;
    const int eg  = tid >> 4;
    const int tt  = blockIdx.x & 127;
    const int ks  = blockIdx.x >> 7;
    const int bt0 = tt * BT;
    const int kbase = ks * KSL;
    const int xcol = tg * 8 + 4 * (tg >> 2);

    float acc[8][8];
#pragma unroll
    for (int i = 0; i < 8; i++)
#pragma unroll
        for (int j = 0; j < 8; j++) acc[i][j] = 0.0f;

    // ---- load chunk 0 ----
#pragma unroll
    for (int i = 0; i < 4; i++) {
        int idx = i * 128 + tid;
        int t = idx >> 2, kq = idx & 3;
        float4 v = *reinterpret_cast<const float4*>(x + (size_t)(bt0 + t) * DM + kbase + kq * 4);
        const int c = XCOL(t);
        xs[(kq * 4 + 0) * XSTR + c] = v.x; xs[(kq * 4 + 1) * XSTR + c] = v.y;
        xs[(kq * 4 + 2) * XSTR + c] = v.z; xs[(kq * 4 + 3) * XSTR + c] = v.w;
    }
#pragma unroll
    for (int i = 0; i < 2; i++) {
        int idx = i * 128 + tid;
        int e = idx >> 2, kq = idx & 3;
        float4 v = *reinterpret_cast<const float4*>(W + (size_t)e * DM + kbase + kq * 4);
        ws[(kq * 4 + 0) * WSTR + e] = v.x; ws[(kq * 4 + 1) * WSTR + e] = v.y;
        ws[(kq * 4 + 2) * WSTR + e] = v.z; ws[(kq * 4 + 3) * WSTR + e] = v.w;
    }
    __syncthreads();

    for (int kc = 0; kc < NCHS; kc++) {
        const int b = kc & 1;
        const float* xb_s = xs + b * (KB * XSTR);
        const float* wb_s = ws + b * (KB * WSTR);

        float4 px[4], pw[2];
        const bool more = (kc + 1 < NCHS);
        if (more) {
            const int k0 = kbase + (kc + 1) * KB;
#pragma unroll
            for (int i = 0; i < 4; i++) {
                int idx = i * 128 + tid;
                int t = idx >> 2, kq = idx & 3;
                px[i] = *reinterpret_cast<const float4*>(x + (size_t)(bt0 + t) * DM + k0 + kq * 4);
            }
#pragma unroll
            for (int i = 0; i < 2; i++) {
                int idx = i * 128 + tid;
                int e = idx >> 2, kq = idx & 3;
                pw[i] = *reinterpret_cast<const float4*>(W + (size_t)e * DM + k0 + kq * 4);
            }
        }

#pragma unroll
        for (int kk = 0; kk < KB; kk++) {
            float4 xa  = *reinterpret_cast<const float4*>(xb_s + kk * XSTR + xcol);
            float4 xv2 = *reinterpret_cast<const float4*>(xb_s + kk * XSTR + xcol + 4);
            float4 wa  = *reinterpret_cast<const float4*>(wb_s + kk * WSTR + eg * 8);
            float4 wv2 = *reinterpret_cast<const float4*>(wb_s + kk * WSTR + eg * 8 + 4);
            float xv[8] = {xa.x, xa.y, xa.z, xa.w, xv2.x, xv2.y, xv2.z, xv2.w};
            float wv[8] = {wa.x, wa.y, wa.z, wa.w, wv2.x, wv2.y, wv2.z, wv2.w};
#pragma unroll
            for (int i = 0; i < 8; i++)
#pragma unroll
                for (int j = 0; j < 8; j++)
                    acc[i][j] = fmaf(xv[i], wv[j], acc[i][j]);
        }

        if (more) {
            const int nb = b ^ 1;
            float* xn = xs + nb * (KB * XSTR);
            float* wn = ws + nb * (KB * WSTR);
#pragma unroll
            for (int i = 0; i < 4; i++) {
                int idx = i * 128 + tid;
                int t = idx >> 2, kq = idx & 3;
                const int c = XCOL(t);
                xn[(kq * 4 + 0) * XSTR + c] = px[i].x; xn[(kq * 4 + 1) * XSTR + c] = px[i].y;
                xn[(kq * 4 + 2) * XSTR + c] = px[i].z; xn[(kq * 4 + 3) * XSTR + c] = px[i].w;
            }
#pragma unroll
            for (int i = 0; i < 2; i++) {
                int idx = i * 128 + tid;
                int e = idx >> 2, kq = idx & 3;
                wn[(kq * 4 + 0) * WSTR + e] = pw[i].x; wn[(kq * 4 + 1) * WSTR + e] = pw[i].y;
                wn[(kq * 4 + 2) * WSTR + e] = pw[i].z; wn[(kq * 4 + 3) * WSTR + e] = pw[i].w;
            }
        }
        __syncthreads();
    }

    // ---- write partials ----
    {
        float* pbase = g_part + ((size_t)ks * NTOK + bt0 + tg * 8) * NE + eg * 8;
#pragma unroll
        for (int i = 0; i < 8; i++) {
            float* row = pbase + (size_t)i * NE;
            *reinterpret_cast<float4*>(row)     = make_float4(acc[i][0], acc[i][1], acc[i][2], acc[i][3]);
            *reinterpret_cast<float4*>(row + 4) = make_float4(acc[i][4], acc[i][5], acc[i][6], acc[i][7]);
        }
    }

    // ---- completion counter ----
    __threadfence();
    __syncthreads();
    if (tid == 0)
        slast = (atomicAdd(&g_tilecnt[tt], 1) == NSPLIT - 1);
    __syncthreads();
    if (!slast) return;

    // ---- last finisher: deterministic reduce + softmax + top2 + z ----
    const int n = bt0 + tid;
    const int lane = tid & 31;

    float L[64];
    const float* p0 = g_part + (size_t)n * NE;
#pragma unroll
    for (int q = 0; q < 16; q++) {
        float4 v = *reinterpret_cast<const float4*>(p0 + 4 * q);
        L[4 * q] = v.x; L[4 * q + 1] = v.y; L[4 * q + 2] = v.z; L[4 * q + 3] = v.w;
    }
#pragma unroll
    for (int s = 1; s < NSPLIT; s++) {
        const float* ps = g_part + ((size_t)s * NTOK + n) * NE;
#pragma unroll
        for (int q = 0; q < 16; q++) {
            float4 v = *reinterpret_cast<const float4*>(ps + 4 * q);
            L[4 * q] += v.x; L[4 * q + 1] += v.y; L[4 * q + 2] += v.z; L[4 * q + 3] += v.w;
        }
    }

    float zacc = 0.0f;
#pragma unroll
    for (int c = 0; c < 64; c++) zacc += L[c] * L[c];
#pragma unroll
    for (int off = 16; off; off >>= 1)
        zacc += __shfl_xor_sync(0xffffffffu, zacc, off);
    if (lane == 0) atomicAdd(&g_zsum, zacc);

    float mx = L[0];
#pragma unroll
    for (int c = 1; c < 64; c++) mx = fmaxf(mx, L[c]);
    float s = 0.0f;
#pragma unroll
    for (int c = 0; c < 64; c++) { L[c] = __expf(L[c] - mx); s += L[c]; }
    const float inv = 1.0f / s;

    float* op = out_rw + (size_t)n * NE;
#pragma unroll
    for (int q = 0; q < 16; q++)
        *reinterpret_cast<float4*>(op + 4 * q) =
            make_float4(L[4 * q] * inv, L[4 * q + 1] * inv,
                        L[4 * q + 2] * inv, L[4 * q + 3] * inv);

    float v1 = -1.0f, v2 = -1.0f; int i1 = 0, i2 = 0;
#pragma unroll
    for (int c = 0; c < 64; c++) {
        const float pv = L[c];
        if (pv > v1)      { v2 = v1; i2 = i1; v1 = pv; i1 = c; }
        else if (pv > v2) { v2 = pv; i2 = c; }
    }
    const float w1 = v1 * inv, w2 = v2 * inv;
    const float den = w1 + w2 + 1e-8f;
    g_e12[n] = i1 | (i2 << 8);
    g_w12[2 * n]     = w1 / den;
    g_w12[2 * n + 1] = w2 / den;
    atomicAdd(&g_cnt1[i1], 1);

    if (tid == 0) g_tilecnt[tt] = 0;
}

// ---------------- stage B: dispatch + counts + (last block) loss + reset ----------------
#define NDBLK ((NTOK * 16) / 256)   // 1024

__global__ __launch_bounds__(256) void dispatch_loss_kernel(
    float* __restrict__ out_nd, float* __restrict__ out_loss)
{
    __shared__ int slast;

    const int gt = blockIdx.x * 256 + threadIdx.x;
    const int token = gt >> 4;
    const int c4 = gt & 15;

    const int e12 = g_e12[token];
    const int e1 = e12 & 0xff, e2 = (e12 >> 8) & 0xff;
    const float w1n = g_w12[2 * token];
    const float w2n = g_w12[2 * token + 1];
    const bool acc2 = (g_cnt1[e2] < CAP);
    const float den = w1n + (acc2 ? w2n : 0.0f) + 1e-8f;
    const float d1 = w1n / den;
    const float d2 = acc2 ? (w2n / den) : 0.0f;

    float4 v = make_float4(0.f, 0.f, 0.f, 0.f);
    const int c0 = c4 * 4;
    int r1 = e1 - c0;
    if (r1 == 0) v.x = d1; else if (r1 == 1) v.y = d1;
    else if (r1 == 2) v.z = d1; else if (r1 == 3) v.w = d1;
    int r2 = e2 - c0;
    if (r2 == 0) v.x = d2; else if (r2 == 1) v.y = d2;
    else if (r2 == 2) v.z = d2; else if (r2 == 3) v.w = d2;

    *reinterpret_cast<float4*>(out_nd + (size_t)token * NE + c0) = v;

    if (c4 == 0) {
        atomicAdd(&g_counts[e1], d1);
        if (acc2) atomicAdd(&g_counts[e2], d2);
    }

    __threadfence();
    __syncthreads();
    if (threadIdx.x == 0)
        slast = (atomicAdd(&g_done, 1) == NDBLK - 1);
    __syncthreads();
    if (!slast) return;

    const int t = threadIdx.x;
    if (t < 32) {
        const float invN = 1.0f / (float)NTOK;
        const float tgt = 512.0f / (float)NTOK;
        float d0 = g_counts[t] * invN - tgt;
        float dd1 = g_counts[t + 32] * invN - tgt;
        float s = d0 * d0 + dd1 * dd1;
#pragma unroll
        for (int off = 16; off; off >>= 1)
            s += __shfl_xor_sync(0xffffffffu, s, off);
        if (t == 0) {
            float lb = s / 64.0f;
            float z = g_zsum / (float)((size_t)NTOK * NE);
            out_loss[0] = 1e-3f * z + 1e-3f * lb;
        }
    }
    __syncthreads();
    if (t < NE) { g_cnt1[t] = 0; g_counts[t] = 0.0f; }
    if (t == 0) { g_zsum = 0.0f; g_done = 0; }
}

// ---------------- launch ----------------
extern "C" void kernel_launch(void* const* d_in, const int* in_sizes, int n_in,
                              void* d_out, int out_size)
{
    const float* x = (const float*)d_in[0];
    const float* W = (const float*)d_in[1];
    if (n_in >= 2 && in_sizes[0] == NE * DM) {
        x = (const float*)d_in[1];
        W = (const float*)d_in[0];
    }
    float* out = (float*)d_out;

    gemm_router<<<NSPLIT * 128, 128>>>(x, W, out);
    dispatch_loss_kernel<<<NDBLK, 256>>>(out + (size_t)NTOK * NE,
                                         out + (size_t)2 * NTOK * NE);
}

// round 14
// speedup vs baseline: 1.1237x; 1.1237x over previous
#include <cuda_runtime.h>
#include <math.h>
#include <stdint.h>

#define NTOK 16384
#define DM   2048
#define NE   64
#define CAP  640
#define BT   128
#define KB   16
#define NSPLIT 8
#define KSL  (DM / NSPLIT)     // 256
#define NCHS (KSL / KB)        // 16

#define XSTR 148
#define WSTR 68
#define XCOL(t) ((t) + 4 * ((t) >> 5))

// ---------------- device scratch (zero-init; reset in-kernel for replays) ----------------
__device__ int   g_e12[NTOK];
__device__ float g_w12[2 * NTOK];
__device__ int   g_cnt1[NE];
__device__ float g_zsum;
__device__ int   g_tilecnt[128];
__device__ int   g_done;
__device__ float g_pcnt[128 * NE];             // per-block count partials
__device__ float g_part[NSPLIT * NTOK * NE];   // 33.5 MB

// ---------------- stage A: K-split GEMM + last-finisher fused reduce/softmax/top2 ----------------
__global__ __launch_bounds__(128) void gemm_router(
    const float* __restrict__ x, const float* __restrict__ W,
    float* __restrict__ out_rw)
{
    __shared__ __align__(16) float xs[2 * KB * XSTR];
    __shared__ __align__(16) float ws[2 * KB * WSTR];
    __shared__ int slast;

    const int tid = threadIdx.x;
    const int tg  = tid & 15;
    const int eg  = tid >> 4;
    const int tt  = blockIdx.x & 127;
    const int ks  = blockIdx.x >> 7;
    const int bt0 = tt * BT;
    const int kbase = ks * KSL;
    const int xcol = tg * 8 + 4 * (tg >> 2);

    float acc[8][8];
#pragma unroll
    for (int i = 0; i < 8; i++)
#pragma unroll
        for (int j = 0; j < 8; j++) acc[i][j] = 0.0f;

#pragma unroll
    for (int i = 0; i < 4; i++) {
        int idx = i * 128 + tid;
        int t = idx >> 2, kq = idx & 3;
        float4 v = *reinterpret_cast<const float4*>(x + (size_t)(bt0 + t) * DM + kbase + kq * 4);
        const int c = XCOL(t);
        xs[(kq * 4 + 0) * XSTR + c] = v.x; xs[(kq * 4 + 1) * XSTR + c] = v.y;
        xs[(kq * 4 + 2) * XSTR + c] = v.z; xs[(kq * 4 + 3) * XSTR + c] = v.w;
    }
#pragma unroll
    for (int i = 0; i < 2; i++) {
        int idx = i * 128 + tid;
        int e = idx >> 2, kq = idx & 3;
        float4 v = *reinterpret_cast<const float4*>(W + (size_t)e * DM + kbase + kq * 4);
        ws[(kq * 4 + 0) * WSTR + e] = v.x; ws[(kq * 4 + 1) * WSTR + e] = v.y;
        ws[(kq * 4 + 2) * WSTR + e] = v.z; ws[(kq * 4 + 3) * WSTR + e] = v.w;
    }
    __syncthreads();

    for (int kc = 0; kc < NCHS; kc++) {
        const int b = kc & 1;
        const float* xb_s = xs + b * (KB * XSTR);
        const float* wb_s = ws + b * (KB * WSTR);

        float4 px[4], pw[2];
        const bool more = (kc + 1 < NCHS);
        if (more) {
            const int k0 = kbase + (kc + 1) * KB;
#pragma unroll
            for (int i = 0; i < 4; i++) {
                int idx = i * 128 + tid;
                int t = idx >> 2, kq = idx & 3;
                px[i] = *reinterpret_cast<const float4*>(x + (size_t)(bt0 + t) * DM + k0 + kq * 4);
            }
#pragma unroll
            for (int i = 0; i < 2; i++) {
                int idx = i * 128 + tid;
                int e = idx >> 2, kq = idx & 3;
                pw[i] = *reinterpret_cast<const float4*>(W + (size_t)e * DM + k0 + kq * 4);
            }
        }

#pragma unroll
        for (int kk = 0; kk < KB; kk++) {
            float4 xa  = *reinterpret_cast<const float4*>(xb_s + kk * XSTR + xcol);
            float4 xv2 = *reinterpret_cast<const float4*>(xb_s + kk * XSTR + xcol + 4);
            float4 wa  = *reinterpret_cast<const float4*>(wb_s + kk * WSTR + eg * 8);
            float4 wv2 = *reinterpret_cast<const float4*>(wb_s + kk * WSTR + eg * 8 + 4);
            float xv[8] = {xa.x, xa.y, xa.z, xa.w, xv2.x, xv2.y, xv2.z, xv2.w};
            float wv[8] = {wa.x, wa.y, wa.z, wa.w, wv2.x, wv2.y, wv2.z, wv2.w};
#pragma unroll
            for (int i = 0; i < 8; i++)
#pragma unroll
                for (int j = 0; j < 8; j++)
                    acc[i][j] = fmaf(xv[i], wv[j], acc[i][j]);
        }

        if (more) {
            const int nb = b ^ 1;
            float* xn = xs + nb * (KB * XSTR);
            float* wn = ws + nb * (KB * WSTR);
#pragma unroll
            for (int i = 0; i < 4; i++) {
                int idx = i * 128 + tid;
                int t = idx >> 2, kq = idx & 3;
                const int c = XCOL(t);
                xn[(kq * 4 + 0) * XSTR + c] = px[i].x; xn[(kq * 4 + 1) * XSTR + c] = px[i].y;
                xn[(kq * 4 + 2) * XSTR + c] = px[i].z; xn[(kq * 4 + 3) * XSTR + c] = px[i].w;
            }
#pragma unroll
            for (int i = 0; i < 2; i++) {
                int idx = i * 128 + tid;
                int e = idx >> 2, kq = idx & 3;
                wn[(kq * 4 + 0) * WSTR + e] = pw[i].x; wn[(kq * 4 + 1) * WSTR + e] = pw[i].y;
                wn[(kq * 4 + 2) * WSTR + e] = pw[i].z; wn[(kq * 4 + 3) * WSTR + e] = pw[i].w;
            }
        }
        __syncthreads();
    }

    {
        float* pbase = g_part + ((size_t)ks * NTOK + bt0 + tg * 8) * NE + eg * 8;
#pragma unroll
        for (int i = 0; i < 8; i++) {
            float* row = pbase + (size_t)i * NE;
            *reinterpret_cast<float4*>(row)     = make_float4(acc[i][0], acc[i][1], acc[i][2], acc[i][3]);
            *reinterpret_cast<float4*>(row + 4) = make_float4(acc[i][4], acc[i][5], acc[i][6], acc[i][7]);
        }
    }

    __threadfence();
    __syncthreads();
    if (tid == 0)
        slast = (atomicAdd(&g_tilecnt[tt], 1) == NSPLIT - 1);
    __syncthreads();
    if (!slast) return;

    const int n = bt0 + tid;
    const int lane = tid & 31;

    float L[64];
    const float* p0 = g_part + (size_t)n * NE;
#pragma unroll
    for (int q = 0; q < 16; q++) {
        float4 v = *reinterpret_cast<const float4*>(p0 + 4 * q);
        L[4 * q] = v.x; L[4 * q + 1] = v.y; L[4 * q + 2] = v.z; L[4 * q + 3] = v.w;
    }
#pragma unroll
    for (int s = 1; s < NSPLIT; s++) {
        const float* ps = g_part + ((size_t)s * NTOK + n) * NE;
#pragma unroll
        for (int q = 0; q < 16; q++) {
            float4 v = *reinterpret_cast<const float4*>(ps + 4 * q);
            L[4 * q] += v.x; L[4 * q + 1] += v.y; L[4 * q + 2] += v.z; L[4 * q + 3] += v.w;
        }
    }

    float zacc = 0.0f;
#pragma unroll
    for (int c = 0; c < 64; c++) zacc += L[c] * L[c];
#pragma unroll
    for (int off = 16; off; off >>= 1)
        zacc += __shfl_xor_sync(0xffffffffu, zacc, off);
    if (lane == 0) atomicAdd(&g_zsum, zacc);

    float mx = L[0];
#pragma unroll
    for (int c = 1; c < 64; c++) mx = fmaxf(mx, L[c]);
    float s = 0.0f;
#pragma unroll
    for (int c = 0; c < 64; c++) { L[c] = __expf(L[c] - mx); s += L[c]; }
    const float inv = 1.0f / s;

    float* op = out_rw + (size_t)n * NE;
#pragma unroll
    for (int q = 0; q < 16; q++)
        *reinterpret_cast<float4*>(op + 4 * q) =
            make_float4(L[4 * q] * inv, L[4 * q + 1] * inv,
                        L[4 * q + 2] * inv, L[4 * q + 3] * inv);

    float v1 = -1.0f, v2 = -1.0f; int i1 = 0, i2 = 0;
#pragma unroll
    for (int c = 0; c < 64; c++) {
        const float pv = L[c];
        if (pv > v1)      { v2 = v1; i2 = i1; v1 = pv; i1 = c; }
        else if (pv > v2) { v2 = pv; i2 = c; }
    }
    const float w1 = v1 * inv, w2 = v2 * inv;
    const float den = w1 + w2 + 1e-8f;
    g_e12[n] = i1 | (i2 << 8);
    g_w12[2 * n]     = w1 / den;
    g_w12[2 * n + 1] = w2 / den;
    atomicAdd(&g_cnt1[i1], 1);

    if (tid == 0) g_tilecnt[tt] = 0;
}

// ---------------- stage B: dispatch (1 thr/token) + partial counts + last-block loss ----------------
#define NDBLK 128

__global__ __launch_bounds__(128) void dispatch_loss_kernel(
    float* __restrict__ out_nd, float* __restrict__ out_loss)
{
    __shared__ float scnt[NE];
    __shared__ int slast;

    const int tid = threadIdx.x;
    const int token = blockIdx.x * 128 + tid;

    if (tid < NE) scnt[tid] = 0.0f;
    __syncthreads();

    const int e12 = g_e12[token];
    const int e1 = e12 & 0xff, e2 = (e12 >> 8) & 0xff;
    const float w1n = g_w12[2 * token];
    const float w2n = g_w12[2 * token + 1];
    const bool acc2 = (g_cnt1[e2] < CAP);
    const float den = w1n + (acc2 ? w2n : 0.0f) + 1e-8f;
    const float d1 = w1n / den;
    const float d2 = acc2 ? (w2n / den) : 0.0f;

    // zero row then scatter the two entries (same-thread ordering)
    float* row = out_nd + (size_t)token * NE;
    const float4 z4 = make_float4(0.f, 0.f, 0.f, 0.f);
#pragma unroll
    for (int q = 0; q < 16; q++)
        *reinterpret_cast<float4*>(row + 4 * q) = z4;
    row[e1] = d1;
    if (acc2) row[e2] = d2;

    // block-local count accumulation (shared atomics, 64 banks)
    atomicAdd(&scnt[e1], d1);
    if (acc2) atomicAdd(&scnt[e2], d2);
    __syncthreads();
    if (tid < NE) g_pcnt[blockIdx.x * NE + tid] = scnt[tid];

    // last-block: reduce partials (fixed order), loss, reset
    __threadfence();
    __syncthreads();
    if (tid == 0)
        slast = (atomicAdd(&g_done, 1) == NDBLK - 1);
    __syncthreads();
    if (!slast) return;

    if (tid < NE) {
        float cnt = 0.0f;
        for (int b = 0; b < NDBLK; b++)
            cnt += g_pcnt[b * NE + tid];

        const float invN = 1.0f / (float)NTOK;
        const float tgt = 512.0f / (float)NTOK;
        float d = cnt * invN - tgt;
        float s = d * d;
#pragma unroll
        for (int off = 16; off; off >>= 1)
            s += __shfl_xor_sync(0xffffffffu, s, off);
        if (tid == 0 || tid == 32) {
            // lane0 of each half-warp holds its 32-expert sum; combine via smem
            scnt[tid] = s;
        }
    }
    __syncthreads();
    if (tid == 0) {
        float lb = (scnt[0] + scnt[32]) / 64.0f;
        float z = g_zsum / (float)((size_t)NTOK * NE);
        out_loss[0] = 1e-3f * z + 1e-3f * lb;
        g_zsum = 0.0f; g_done = 0;
    }
    if (tid < NE) g_cnt1[tid] = 0;
}

// ---------------- launch ----------------
extern "C" void kernel_launch(void* const* d_in, const int* in_sizes, int n_in,
                              void* d_out, int out_size)
{
    const float* x = (const float*)d_in[0];
    const float* W = (const float*)d_in[1];
    if (n_in >= 2 && in_sizes[0] == NE * DM) {
        x = (const float*)d_in[1];
        W = (const float*)d_in[0];
    }
    float* out = (float*)d_out;

    gemm_router<<<NSPLIT * 128, 128>>>(x, W, out);
    dispatch_loss_kernel<<<NDBLK, 128>>>(out + (size_t)NTOK * NE,
                                         out + (size_t)2 * NTOK * NE);
}